// round 17
// baseline (speedup 1.0000x reference)
#include <cuda_runtime.h>
#include <math.h>

#define Nn 8
#define Tt 64
#define Aa 65536
#define Cc 80
#define NFLT4 (Aa * (Cc / 4))          // float4s of y_pred per image = 1,310,720
#define ITER 8
#define SBX_PER_N 640                   // stream blocks per image
#define SBb (SBX_PER_N * Nn)            // 5120 stream blocks
#define AB ((Aa / 256) * Nn)            // 2048 assignment blocks
#define CB 2048                         // correction blocks
#define TOTB (AB + SBb + CB + 1)        // + 1 final block

#define F_EPS 1e-6f
#define SL1_BETA (1.0f / 9.0f)
#define LN2 0.69314718055994531f
#define FOCAL_SCALE (0.75f * 0.69314718056f)   // 0.75 * ln2
#define IGN_FLAG (1 << 30)

// ---------------- scratch (device globals; no allocation) ----------------
__device__ int            g_state[Nn * Aa];   // 0=ignore 1=neg 2=pos
__device__ int            g_asg[Nn * Aa];     // bit30 = override, low bits = gt index t
__device__ int            g_nvalid[Nn];
__device__ unsigned char  g_vt[Nn * Tt];
__device__ unsigned char  g_label[Nn * Tt];
__device__ unsigned long long g_gtkey[Nn * Tt];
__device__ int            g_poscnt[Nn];
__device__ __align__(16) float g_pcls[SBb];
__device__ __align__(16) float g_qcls[CB];
__device__ __align__(16) float g_qbox[CB];
__device__ int            g_ignlist[Nn * Aa];
__device__ int            g_poslist[Nn * Aa];
__device__ int            g_nign;
__device__ int            g_npos;
__device__ unsigned       g_done1;    // assignment blocks completed
__device__ unsigned       g_lqdone;   // LQ tail complete (lists final)
__device__ unsigned       g_doneS;    // stream blocks completed
__device__ unsigned       g_doneC;    // correction blocks completed

// ---------------- helpers ----------------
__device__ __forceinline__ float rcp_approx(float x) {
    float r; asm("rcp.approx.f32 %0, %1;" : "=f"(r) : "f"(x)); return r;
}
__device__ __forceinline__ float ex2a(float x) {
    float r; asm("ex2.approx.f32 %0, %1;" : "=f"(r) : "f"(x)); return r;
}
__device__ __forceinline__ float lg2a(float x) {
    float r; asm("lg2.approx.f32 %0, %1;" : "=f"(r) : "f"(x)); return r;
}

// Sign-free focal accumulate: acc += p^2 * lg2(1+e^l)  (FFMA-folded)
// Full focal term = FOCAL_SCALE * (p^2 * lg2(1+e^l)) = 0.75 * p^2 * softplus(l).
// 12 SASS instr, 2 MUFU (EX2, LG2); reciprocal via bit-seed + 2 Newton.
__device__ __forceinline__ float focal_acc(float l, float acc) {
    float z = ex2a(l * 1.44269504f);                 // e^l
    float u = 1.0f + z;                              // (1, inf)
    float r = __int_as_float(0x7EF311C3 - __float_as_int(u));
    r = r * fmaf(-u, r, 2.0f);                       // Newton 1
    r = r * fmaf(-u, r, 2.0f);                       // Newton 2: rel err ~6e-6
    float zr = z * r;                                // p = sigmoid(l)
    return fmaf(zr * zr, lg2a(u), acc);              // acc += p^2 * lg2(1+e^l)
}
__device__ __forceinline__ float focal_t(float l) { return focal_acc(l, 0.0f); }

__device__ __forceinline__ void spin_ge(volatile unsigned* p, unsigned v) {
    while (*p < v) __nanosleep(200);
}

// ---------------- single fused launch; 32 regs for full occupancy ----------------
__global__ void __launch_bounds__(256, 8)
kAll(const float4* __restrict__ anchors,
     const float4* __restrict__ bb,
     const float* __restrict__ y_true,
     const float4* __restrict__ yp4,
     const float4* __restrict__ bbp4,
     const float* __restrict__ bbox_true,
     float* __restrict__ out) {
    int bid = blockIdx.x;
    int tid = threadIdx.x;

    // ================= STREAM BLOCKS =================
    if (bid >= AB && bid < AB + SBb) {
        int sb = bid - AB;
        int n = sb / SBX_PER_N;
        int bx = sb - n * SBX_PER_N;
        const float4* yp = yp4 + (size_t)n * NFLT4 + bx * (256 * ITER);
        float acc0 = 0.f, acc1 = 0.f;
        #pragma unroll
        for (int i = 0; i < ITER; i++) {
            float4 vv = yp[i * 256 + tid];
            acc0 = focal_acc(vv.x, acc0);
            acc1 = focal_acc(vv.y, acc1);
            acc0 = focal_acc(vv.z, acc0);
            acc1 = focal_acc(vv.w, acc1);
        }
        float clsl = acc0 + acc1;
        unsigned full = 0xFFFFFFFFu;
        #pragma unroll
        for (int o = 16; o > 0; o >>= 1)
            clsl += __shfl_down_sync(full, clsl, o);
        __shared__ float wc[8];
        int w = tid >> 5, lane = tid & 31;
        if (lane == 0) wc[w] = clsl;
        __syncthreads();
        if (tid == 0) {
            float c = 0.f;
            #pragma unroll
            for (int i = 0; i < 8; i++) c += wc[i];
            g_pcls[sb] = FOCAL_SCALE * c;
            __threadfence();
            atomicAdd(&g_doneS, 1u);
        }
        return;
    }

    // ================= CORRECTION BLOCKS =================
    if (bid >= AB + SBb && bid < AB + SBb + CB) {
        int cb = bid - AB - SBb;
        if (tid == 0) spin_ge(&g_lqdone, 1u);       // lists final after LQ tail
        __syncthreads();
        __threadfence();

        float cls = 0.f, box = 0.f;
        int gtid = cb * 256 + tid;
        const int stride = CB * 256;

        int nI = g_nign;
        int nItems = nI * 20;
        #pragma unroll 4
        for (int it = gtid; it < nItems; it += stride) {
            int e = it / 20;
            int qq = it - e * 20;
            int idx = g_ignlist[e];
            int n = idx >> 16;
            int a = idx & (Aa - 1);
            float4 vv = yp4[(size_t)n * NFLT4 + (size_t)a * 20 + qq];
            float S = 0.f;
            S = focal_acc(vv.x, S); S = focal_acc(vv.y, S);
            S = focal_acc(vv.z, S); S = focal_acc(vv.w, S);
            cls = fmaf(-FOCAL_SCALE, S, cls);
        }

        int nP = g_npos;
        for (int e = gtid; e < nP; e += stride) {
            int ent = g_poslist[e];
            int idx = ent & ~IGN_FLAG;
            int n = idx >> 16;
            int a = idx & (Aa - 1);
            const float4* yp = yp4 + (size_t)n * NFLT4 + (size_t)a * 20;

            if (ent & IGN_FLAG) {
                // was on the ignore list; its focal sum was subtracted above -> add back
                float S = 0.f;
                #pragma unroll 4
                for (int qq = 0; qq < 20; qq++) {
                    float4 vv = yp[qq];
                    S = focal_acc(vv.x, S); S = focal_acc(vv.y, S);
                    S = focal_acc(vv.z, S); S = focal_acc(vv.w, S);
                }
                cls = fmaf(FOCAL_SCALE, S, cls);
            }

            int v = g_asg[idx];
            int asg = (v & 0x40000000) ? (v & 0xFF) : v;
            int label = (int)g_label[n * Tt + asg];
            float4 vv = yp[label >> 2];
            int j = label & 3;
            float lsel = (j == 0) ? vv.x : ((j == 1) ? vv.y : ((j == 2) ? vv.z : vv.w));
            {
                // + alpha*q^2*softplus(-l)  (accurate path; rare)
                float mm = fabsf(lsel);
                float em = __expf(-mm);
                float uu = 1.0f + em;
                float r  = rcp_approx(uu);
                float lgv = __logf(uu);
                float p  = (lsel >= 0.f) ? r : em * r;
                float qd = 1.0f - p;
                float cep = lgv + fmaxf(-lsel, 0.f);
                // - stream's contribution for the label element (cancel)
                cls += 0.25f * qd * qd * cep - FOCAL_SCALE * focal_t(lsel);
            }
            float4 an = anchors[a];
            float4 bp = bbp4[idx];
            const float* bt = bbox_true + ((size_t)n * Tt + asg) * 4;
            float bx1 = bt[0], by1 = bt[1], bx2 = bt[2], by2 = bt[3];
            float wa = fmaxf(an.z - an.x, F_EPS);
            float ha = fmaxf(an.w - an.y, F_EPS);
            float cxa = an.x + 0.5f * wa;
            float cya = an.y + 0.5f * ha;
            float wt = fmaxf(bx2 - bx1, F_EPS);
            float ht = fmaxf(by2 - by1, F_EPS);
            float cxt = bx1 + 0.5f * (bx2 - bx1);
            float cyt = by1 + 0.5f * (by2 - by1);
            float tg0 = (cxt - cxa) / wa;
            float tg1 = (cyt - cya) / ha;
            float tg2 = logf(wt / wa);
            float tg3 = logf(ht / ha);
            float d0 = fabsf(tg0 - bp.x), d1 = fabsf(tg1 - bp.y);
            float d2 = fabsf(tg2 - bp.z), d3 = fabsf(tg3 - bp.w);
            box += (d0 < SL1_BETA) ? (0.5f * d0 * d0 / SL1_BETA) : (d0 - 0.5f * SL1_BETA);
            box += (d1 < SL1_BETA) ? (0.5f * d1 * d1 / SL1_BETA) : (d1 - 0.5f * SL1_BETA);
            box += (d2 < SL1_BETA) ? (0.5f * d2 * d2 / SL1_BETA) : (d2 - 0.5f * SL1_BETA);
            box += (d3 < SL1_BETA) ? (0.5f * d3 * d3 / SL1_BETA) : (d3 - 0.5f * SL1_BETA);
        }

        unsigned full = 0xFFFFFFFFu;
        #pragma unroll
        for (int o = 16; o > 0; o >>= 1) {
            cls += __shfl_down_sync(full, cls, o);
            box += __shfl_down_sync(full, box, o);
        }
        __shared__ float wc[8], wb[8];
        int w = tid >> 5, lane = tid & 31;
        if (lane == 0) { wc[w] = cls; wb[w] = box; }
        __syncthreads();
        if (tid == 0) {
            float c = 0.f, b = 0.f;
            #pragma unroll
            for (int i = 0; i < 8; i++) { c += wc[i]; b += wb[i]; }
            g_qcls[cb] = c;
            g_qbox[cb] = b;
            __threadfence();
            atomicAdd(&g_doneC, 1u);
        }
        return;
    }

    // ================= FINAL BLOCK =================
    if (bid == AB + SBb + CB) {
        if (tid == 0) {
            spin_ge(&g_doneS, (unsigned)SBb);
            spin_ge(&g_doneC, (unsigned)CB);
        }
        __syncthreads();
        __threadfence();

        __shared__ double sc[256], sb2[256];
        double c = 0.0, b = 0.0;
        {
            const float4* pc4 = (const float4*)g_pcls;     // 1280
            #pragma unroll 5
            for (int i = tid; i < SBb / 4; i += 256) {
                float4 v = pc4[i];
                c += (double)((v.x + v.y) + (v.z + v.w));
            }
            const float4* qc4 = (const float4*)g_qcls;     // 512
            const float4* qb4 = (const float4*)g_qbox;
            #pragma unroll 2
            for (int i = tid; i < CB / 4; i += 256) {
                float4 v = qc4[i];
                float4 u = qb4[i];
                c += (double)((v.x + v.y) + (v.z + v.w));
                b += (double)((u.x + u.y) + (u.z + u.w));
            }
        }
        sc[tid] = c; sb2[tid] = b;
        __syncthreads();
        for (int s = 128; s > 0; s >>= 1) {
            if (tid < s) { sc[tid] += sc[tid + s]; sb2[tid] += sb2[tid + s]; }
            __syncthreads();
        }
        if (tid == 0) {
            double avg = 0.0;
            for (int nn = 0; nn < Nn; nn++) {
                double p = (double)g_poscnt[nn];
                avg += (p > 1.0) ? p : 1.0;
            }
            float clsO = (float)(sc[0] / avg);
            float boxO = (float)(sb2[0] / avg);
            if (isnan(clsO) || isinf(clsO)) clsO = 0.f;
            if (isnan(boxO) || isinf(boxO)) boxO = 0.f;
            out[0] = clsO;
            out[1] = boxO;
        }
        __syncthreads();
        // resets for next graph replay
        if (tid == 0) {
            g_done1 = 0; g_lqdone = 0; g_doneS = 0; g_doneC = 0;
            g_npos = 0; g_nign = 0;
        }
        if (tid < Nn) g_poscnt[tid] = 0;
        for (int i = tid; i < Nn * Tt; i += 256) g_gtkey[i] = 0ull;
        return;
    }

    // ================= ASSIGNMENT BLOCKS (bid < AB) =================
    int n = bid >> 8;
    int axb = bid & 255;

    __shared__ float4 sbox[Tt];
    __shared__ float  sarea[Tt];
    __shared__ unsigned char svt[Tt];
    __shared__ unsigned long long swkey[8][Tt];
    __shared__ unsigned smask[2];
    __shared__ int snv;

    float4 myb; bool myvalid = false; unsigned mk = 0;
    if (tid < 64) {
        myb = bb[n * Tt + tid];
        myvalid = (myb.x > 0.f) || (myb.y > 0.f) || (myb.z > 0.f) || (myb.w > 0.f);
        mk = __ballot_sync(0xFFFFFFFFu, myvalid);
        if ((tid & 31) == 0) smask[tid >> 5] = mk;
    }
    if (axb == 0 && tid >= 64 && tid < 128) {
        int r = n * Tt + (tid - 64);
        const float4* row = (const float4*)(y_true + (size_t)r * Cc);
        int lab = 0;
        #pragma unroll 4
        for (int qq = 0; qq < Cc / 4; qq++) {
            float4 v = row[qq];
            if (v.x > 0.5f) lab = 4 * qq;
            if (v.y > 0.5f) lab = 4 * qq + 1;
            if (v.z > 0.5f) lab = 4 * qq + 2;
            if (v.w > 0.5f) lab = 4 * qq + 3;
        }
        g_label[r] = (unsigned char)lab;
    }
    __syncthreads();
    if (tid < 64 && myvalid) {
        int pos = __popc(mk & ((1u << (tid & 31)) - 1)) +
                  ((tid >= 32) ? __popc(smask[0]) : 0);
        sbox[pos]  = myb;
        sarea[pos] = fmaxf(myb.z - myb.x, 0.f) * fmaxf(myb.w - myb.y, 0.f);
        svt[pos]   = (unsigned char)tid;
        if (axb == 0) g_vt[n * Tt + pos] = (unsigned char)tid;
    }
    if (tid == 0) {
        snv = __popc(smask[0]) + __popc(smask[1]);
        if (axb == 0) g_nvalid[n] = snv;
    }
    __syncthreads();
    int nv = snv;

    int a = axb * 256 + tid;
    float4 an = anchors[a];
    float a2 = fmaxf(an.z - an.x, 0.f) * fmaxf(an.w - an.y, 0.f);
    unsigned lane = tid & 31;
    int w = tid >> 5;

    float best = -1.0f; int arg = 0;
    for (int k = 0; k < nv; k++) {
        float4 b = sbox[k];
        float lx = fmaxf(b.x, an.x), ly = fmaxf(b.y, an.y);
        float rx = fminf(b.z, an.z), ry = fminf(b.w, an.w);
        float iw = fmaxf(rx - lx, 0.f), ih = fmaxf(ry - ly, 0.f);
        float inter = iw * ih;
        float uni = sarea[k] + a2 - inter;          // > 0 (anchors have wh >= 0.02)
        float iou = __fdividef(inter, uni);         // approx div
        if (iou > best) { best = iou; arg = svt[k]; }  // first-max (smallest t)

        unsigned ib = __float_as_uint(iou);
        unsigned mx = __reduce_max_sync(0xFFFFFFFFu, ib);
        unsigned msk = __ballot_sync(0xFFFFFFFFu, ib == mx);
        if (lane == (unsigned)(__ffs(msk) - 1))
            swkey[w][k] = ((unsigned long long)mx << 32) |
                          (unsigned long long)(~(unsigned)a);
    }
    __syncthreads();

    int idx = n * Aa + a;
    int st = (best >= 0.5f) ? 2 : ((best < 0.4f) ? 1 : 0);
    g_asg[idx]   = arg;
    g_state[idx] = st;

    // warp-aggregated list appends
    {
        unsigned bpos = __ballot_sync(0xFFFFFFFFu, st == 2);
        unsigned bign = __ballot_sync(0xFFFFFFFFu, st == 0);
        unsigned lmask = (1u << lane) - 1u;
        int basep = 0, basei = 0;
        if (lane == 0) {
            if (bpos) {
                basep = atomicAdd(&g_npos, __popc(bpos));
                atomicAdd(&g_poscnt[n], __popc(bpos));
            }
            if (bign) basei = atomicAdd(&g_nign, __popc(bign));
        }
        basep = __shfl_sync(0xFFFFFFFFu, basep, 0);
        basei = __shfl_sync(0xFFFFFFFFu, basei, 0);
        if (st == 2) g_poslist[basep + __popc(bpos & lmask)] = idx;
        if (st == 0) g_ignlist[basei + __popc(bign & lmask)] = idx;
    }

    if (tid < nv) {
        unsigned long long m = swkey[0][tid];
        #pragma unroll
        for (int ww = 1; ww < 8; ww++) {
            unsigned long long o = swkey[ww][tid];
            if (o > m) m = o;
        }
        if ((m >> 32) != 0)
            atomicMax(&g_gtkey[n * Tt + tid], m);
    }

    // fused low-quality override: last finishing assignment block applies all
    __syncthreads();
    __threadfence();
    __shared__ bool slast;
    if (tid == 0)
        slast = (atomicAdd(&g_done1, 1u) == (unsigned)(AB - 1));
    __syncthreads();
    if (slast) {
        for (int idx2 = tid; idx2 < Nn * Tt; idx2 += 256) {
            int nn = idx2 >> 6, k = idx2 & 63;
            if (k < g_nvalid[nn]) {
                unsigned long long key = g_gtkey[nn * Tt + k];
                if ((key >> 32) != 0) {
                    int aa = (int)(~(unsigned)(key & 0xFFFFFFFFull));
                    int t = g_vt[nn * Tt + k];
                    int p = nn * Aa + aa;
                    atomicMax(&g_asg[p], 0x40000000 | t);
                    int old = atomicExch(&g_state[p], 2);
                    if (old != 2) {
                        int pp = atomicAdd(&g_npos, 1);
                        g_poslist[pp] = p | ((old == 0) ? IGN_FLAG : 0);
                        atomicAdd(&g_poscnt[nn], 1);
                    }
                }
            }
        }
        __syncthreads();
        __threadfence();
        if (tid == 0) atomicExch(&g_lqdone, 1u);   // release: lists final
    }
}

// ---------------- launch ----------------
extern "C" void kernel_launch(void* const* d_in, const int* in_sizes, int n_in,
                              void* d_out, int out_size) {
    const float*  y_true    = (const float*)d_in[0];
    const float*  bbox_true = (const float*)d_in[1];
    const float*  y_pred    = (const float*)d_in[2];
    const float4* bbox_pred = (const float4*)d_in[3];
    const float4* anchors   = (const float4*)d_in[4];
    float* out = (float*)d_out;

    kAll<<<TOTB, 256>>>(anchors, (const float4*)bbox_true, y_true,
                        (const float4*)y_pred, bbox_pred, bbox_true, out);
}